// round 14
// baseline (speedup 1.0000x reference)
#include <cuda_runtime.h>
#include <cuda_fp16.h>
#include <math.h>

#define NN 50000
#define EE 800000
#define DDIM 128
#define TT 4
#define HH 8
#define DKV 16
#define HDV 8

#define CSR_BLOCKS ((EE + 127) / 128)        // 6250
#define PROJ_BX ((NN + 31) / 32)             // 1563
#define PROJ_BLOCKS (PROJ_BX * TT)           // 6252
#define K2_BLOCKS (1 + PROJ_BLOCKS + CSR_BLOCKS)
#define EDGE_BLOCKS (148 * 6)                // persistent grid

typedef unsigned long long u64;

// ---------------- scratch (static device memory; no allocation) ----------------
__device__ float  g_q[NN * DDIM];
__device__ __half g_kh[NN * DDIM];           // half k: tanh args AND message source
__device__ float  g_hsub[NN * HH * HDV];
__device__ __half g_hnh[NN * HH * HDV];      // half h_neigh (tanh args)
__device__ __half g_Wh[2 * TT * DDIM * DDIM]; // fp16 W, [mat][t][o][k] (transposed)
__device__ int    g_zeroed[2 * NN + TT + 2]; // [deg | cnt | tcount | ticket | scandone]
#define G_DEG(i)   g_zeroed[i]
#define G_CNT(i)   g_zeroed[NN + (i)]
#define G_TC(i)    g_zeroed[2 * NN + (i)]
#define G_TICKET   (&g_zeroed[2 * NN + TT])
#define G_SCANDONE (&g_zeroed[2 * NN + TT + 1])
__device__ int    g_off[NN + 1];
__device__ int    g_csr[EE];                 // BYTE offset src*512 per CSR slot
__device__ int    g_bucket[TT * NN];

// ---------------- helpers (unique prefix, anon namespace) ----------------
namespace {
__device__ __forceinline__ float hgx_gelu(float x) {
    return 0.5f * x * (1.f + erff(x * 0.7071067811865475f));
}
__device__ __forceinline__ u64 hgx_pack2(float lo, float hi) {
    u64 r; asm("mov.b64 %0, {%1, %2};" : "=l"(r) : "f"(lo), "f"(hi)); return r;
}
__device__ __forceinline__ void hgx_unpack2(u64 v, float& lo, float& hi) {
    asm("mov.b64 {%0, %1}, %2;" : "=f"(lo), "=f"(hi) : "l"(v));
}
__device__ __forceinline__ u64 hgx_ffma2(u64 a, u64 b, u64 c) {
    u64 d; asm("fma.rn.f32x2 %0, %1, %2, %3;" : "=l"(d) : "l"(a), "l"(b), "l"(c)); return d;
}
__device__ __forceinline__ __half2 hgx_tanh2(__half2 x) {
    unsigned xi = *reinterpret_cast<unsigned*>(&x);
    unsigned yi;
    asm("tanh.approx.f16x2 %0, %1;" : "=r"(yi) : "r"(xi));
    return *reinterpret_cast<__half2*>(&yi);
}
__device__ __forceinline__ __half2 hgx_shfl_xor_h2(__half2 v, int m) {
    unsigned u = *reinterpret_cast<unsigned*>(&v);
    u = __shfl_xor_sync(0xffffffffu, u, m);
    return *reinterpret_cast<__half2*>(&u);
}

// per-edge core: one half k stream feeds tanh args AND (reconverted) message
__device__ __forceinline__ void hgx_edge(
        int o, const char* khbase, const char* hnbase,
        __half2 qh0, __half2 qh1, __half2 rv0h, __half2 rv1h,
        __half2 hsh, __half2 rhh,
        u64& a01, u64& a23, float& den) {
    const float C = 0.08838834764831845f;    // 1/(4*sqrt(8))
    uint2 khp = *(const uint2*)(khbase + (o >> 1));         // 4 half k (8B)
    unsigned hnu = *(const unsigned*)(hnbase + (o >> 2));   // 2 half hneigh (4B)
    __half2 kh0 = *reinterpret_cast<__half2*>(&khp.x);
    __half2 kh1 = *reinterpret_cast<__half2*>(&khp.y);
    __half2 hnh = *reinterpret_cast<__half2*>(&hnu);

    __half2 ta = __hmul2(hgx_tanh2(__hmul2(qh0, kh0)), rv0h);
    ta = __hfma2(hgx_tanh2(__hmul2(qh1, kh1)), rv1h, ta);
    __half2 tb = __hmul2(hgx_tanh2(__hmul2(hsh, hnh)), rhh);

    __half2 sab = __hadd2(__lows2half2(ta, tb), __highs2half2(ta, tb));
    sab = __hadd2(sab, hgx_shfl_xor_h2(sab, 1));
    sab = __hadd2(sab, hgx_shfl_xor_h2(sab, 2));

    float2 f = __half22float2(sab);
    float w = __expf(f.x * f.y * C);
    den += w;
    float2 f0 = __half22float2(kh0);
    float2 f1 = __half22float2(kh1);
    u64 w2 = hgx_pack2(w, w);
    a01 = hgx_ffma2(hgx_pack2(f0.x, f0.y), w2, a01);
    a23 = hgx_ffma2(hgx_pack2(f1.x, f1.y), w2, a23);
}
} // anonymous namespace

// ---------------- k1: h projections + W fp16 transpose + degree + bucketing ----------------
__global__ void k_pre(const int* __restrict__ ei, const int* __restrict__ ntype,
                      const float* __restrict__ h_mat,
                      const float* __restrict__ hsW, const float* __restrict__ hsb,
                      const float* __restrict__ hnW, const float* __restrict__ hnb,
                      const float* __restrict__ subW, const float* __restrict__ neighW) {
    __shared__ int s_cnt[TT], s_base[TT];
    int idx = blockIdx.x * blockDim.x + threadIdx.x;
    int tid = threadIdx.x;

    if (idx < NN * 64) {
        int n = idx >> 6, j = idx & 63;
        float s1 = hsb[j], s2 = hnb[j];
        const float* hm = h_mat + n * 8;
#pragma unroll
        for (int d = 0; d < 8; d++) {
            float v = hm[d];
            s1 += v * hsW[d * 64 + j];
            s2 += v * hnW[d * 64 + j];
        }
        g_hsub[idx] = s1;
        g_hnh[idx] = __float2half_rn(s2);
    }

    // fp16 weight transpose: g_Wh[mat][t][o][k] = W[t][k][o]
    if (idx < 2 * TT * DDIM * DDIM) {
        int mat = idx >> 16;              // /65536
        int r = idx & 65535;
        int t = r >> 14;                  // /16384
        int rem = r & 16383;
        int o = rem >> 7;
        int k = rem & 127;
        const float* W = mat ? neighW : subW;
        g_Wh[idx] = __float2half_rn(W[t * 16384 + k * 128 + o]);
    }

    if (tid < TT) s_cnt[tid] = 0;
    __syncthreads();

    if (idx < EE) atomicAdd(&G_DEG(ei[EE + idx]), 1);

    int t = -1, pos = 0;
    if (idx < NN) {
        t = ntype[idx];
        pos = atomicAdd(&s_cnt[t], 1);
    }
    __syncthreads();
    if (tid < TT && s_cnt[tid] > 0)
        s_base[tid] = atomicAdd(&G_TC(tid), s_cnt[tid]);
    __syncthreads();
    if (idx < NN) g_bucket[t * NN + s_base[t] + pos] = idx;
}

// ---------------- k2: scan (block 0) | mma.sync projection | CSR fill ----------------
__global__ __launch_bounds__(128) void k_mid(
        const float* __restrict__ xs,
        const float* __restrict__ subb, const float* __restrict__ neighb,
        const int* __restrict__ ei) {
    const int blk = blockIdx.x;
    const int tid = threadIdx.x;

    // ---- role 0: single-block degree prefix scan (hidden under proj blocks)
    if (blk == 0) {
        __shared__ int sums[128];
        const int CH = (NN + 127) / 128;     // 391
        int b = tid * CH;
        int e = min(b + CH, NN);
        int s = 0;
        for (int i = b; i < e; i++) s += G_DEG(i);
        sums[tid] = s;
        __syncthreads();
        for (int off = 1; off < 128; off <<= 1) {
            int v = (tid >= off) ? sums[tid - off] : 0;
            __syncthreads();
            sums[tid] += v;
            __syncthreads();
        }
        int run = sums[tid] - s;
        for (int i = b; i < e; i++) { g_off[i] = run; run += G_DEG(i); }
        if (tid == 127) g_off[NN] = sums[127];
        __syncthreads();
        if (tid == 0) {
            __threadfence();
            atomicExch(G_SCANDONE, 1);
        }
        return;
    }

    // ---- role 2 (trailing blocks): CSR fill; spin until scan published g_off
    if (blk > PROJ_BLOCKS) {
        if (tid == 0) {
            while (atomicAdd(G_SCANDONE, 0) == 0) __nanosleep(200);
        }
        __syncthreads();
        int i = (blk - 1 - PROJ_BLOCKS) * 128 + tid;
        if (i < EE) {
            int src = ei[i];
            int dst = ei[EE + i];
            int pos = g_off[dst] + atomicAdd(&G_CNT(dst), 1);
            g_csr[pos] = src * 512;          // byte offset (fp32 row scale; >>1 for kh)
        }
        return;
    }

    // ---- role 1: fp16 mma.sync projection; block = 32 nodes of ONE type, 4 warps
    const int pb = blk - 1;
    const int t = pb / PROJ_BX;
    const int base = (pb % PROJ_BX) * 32;
    const int cnt = G_TC(t);
    if (base >= cnt) return;
    const int m = min(32, cnt - base);

    // padded stride 136 halfs (272B): conflict-free b32 frag reads, 16B-aligned rows
    __shared__ __half sA[32 * 136];          // x tile [node][k]
    __shared__ __half sB[4][32 * 136];       // per-warp W tile [o][k]
    __shared__ int nd[32];

    const int lane = tid & 31;
    const int warp = tid >> 5;

    if (tid < 32) nd[tid] = (tid < m) ? g_bucket[t * NN + base + tid] : 0;
    __syncthreads();

    // fill A (fp16): 64 threads cover 128 dims, 2 node-groups
    {
        int half_id = tid >> 6;              // 0..1
        int dpair = (tid & 63) * 2;          // even dim
#pragma unroll
        for (int i = 0; i < 16; i++) {
            int node = i * 2 + half_id;
            float2 xv = (node < m) ? *(const float2*)(xs + (size_t)nd[node] * DDIM + dpair)
                                   : make_float2(0.f, 0.f);
            *(__half2*)&sA[node * 136 + dpair] = __floats2half2_rn(xv.x, xv.y);
        }
    }
    __syncthreads();

    const int g = lane >> 2;                 // 0..7
    const int c0 = (lane & 3) * 2;           // 0,2,4,6
    const int wbase = warp * 32;
    __half* sBw = sB[warp];

    for (int mat = 0; mat < 2; mat++) {
        const __half* Wh = g_Wh + ((size_t)mat * TT + t) * (DDIM * DDIM) + (size_t)wbase * DDIM;

        __syncwarp();
        // stage this warp's W tile: 32 o-rows x 128 k halfs (coalesced uint4)
#pragma unroll
        for (int it = 0; it < 16; it++) {
            int idx = it * 32 + lane;        // 0..511 chunks of 8 halfs
            int o = idx >> 4;
            int ch = idx & 15;
            uint4 v = *(const uint4*)(Wh + o * DDIM + ch * 8);
            *(uint4*)&sBw[o * 136 + ch * 8] = v;
        }
        __syncwarp();

        float acc[8][4];                     // [nt*2+mt][4]
#pragma unroll
        for (int i = 0; i < 8; i++)
#pragma unroll
            for (int j = 0; j < 4; j++) acc[i][j] = 0.f;

#pragma unroll
        for (int ks = 0; ks < 8; ks++) {
            int kb = ks * 16;
            unsigned a[2][4], bf[4][2];
#pragma unroll
            for (int mt = 0; mt < 2; mt++) {
                int r0 = mt * 16 + g;
                a[mt][0] = *(const unsigned*)&sA[r0 * 136 + kb + c0];
                a[mt][1] = *(const unsigned*)&sA[(r0 + 8) * 136 + kb + c0];
                a[mt][2] = *(const unsigned*)&sA[r0 * 136 + kb + c0 + 8];
                a[mt][3] = *(const unsigned*)&sA[(r0 + 8) * 136 + kb + c0 + 8];
            }
#pragma unroll
            for (int nt = 0; nt < 4; nt++) {
                int n = nt * 8 + g;
                bf[nt][0] = *(const unsigned*)&sBw[n * 136 + kb + c0];
                bf[nt][1] = *(const unsigned*)&sBw[n * 136 + kb + c0 + 8];
            }
#pragma unroll
            for (int nt = 0; nt < 4; nt++)
#pragma unroll
                for (int mt = 0; mt < 2; mt++) {
                    float* c = acc[nt * 2 + mt];
                    asm volatile(
                        "mma.sync.aligned.m16n8k16.row.col.f32.f16.f16.f32 "
                        "{%0,%1,%2,%3}, {%4,%5,%6,%7}, {%8,%9}, {%0,%1,%2,%3};\n"
                        : "+f"(c[0]), "+f"(c[1]), "+f"(c[2]), "+f"(c[3])
                        : "r"(a[mt][0]), "r"(a[mt][1]), "r"(a[mt][2]), "r"(a[mt][3]),
                          "r"(bf[nt][0]), "r"(bf[nt][1]));
                }
        }

        // epilogue: bias + store (q fp32, k half)
        const float* bias = (mat == 0 ? subb : neighb) + t * DDIM;
#pragma unroll
        for (int nt = 0; nt < 4; nt++) {
            int col = wbase + nt * 8 + c0;
            float2 bb = *(const float2*)(bias + col);
#pragma unroll
            for (int mt = 0; mt < 2; mt++) {
                float* c = acc[nt * 2 + mt];
                int r0 = mt * 16 + g, r1 = r0 + 8;
                if (mat == 0) {
                    if (r0 < m) *(float2*)(g_q + (size_t)nd[r0] * DDIM + col) =
                        make_float2(c[0] + bb.x, c[1] + bb.y);
                    if (r1 < m) *(float2*)(g_q + (size_t)nd[r1] * DDIM + col) =
                        make_float2(c[2] + bb.x, c[3] + bb.y);
                } else {
                    if (r0 < m) *(__half2*)(g_kh + (size_t)nd[r0] * DDIM + col) =
                        __floats2half2_rn(c[0] + bb.x, c[1] + bb.y);
                    if (r1 < m) *(__half2*)(g_kh + (size_t)nd[r1] * DDIM + col) =
                        __floats2half2_rn(c[2] + bb.x, c[3] + bb.y);
                }
            }
        }
    }
}

// ---------------- fused attention + softmax + aggregate + gelu + LN ----------------
// PERSISTENT: warps pull dst nodes via global ticket; lane owns 4 dims (head = lane>>2)
__global__ __launch_bounds__(256, 6) void k_edge(
        const int* __restrict__ ntype,
        const float* __restrict__ ratt, const float* __restrict__ rhatt,
        const float* __restrict__ gamma, const float* __restrict__ beta,
        float* __restrict__ out) {
    const int lane = threadIdx.x & 31;
    const int h = lane >> 2;
    const int qd = lane & 3;

    const char* khbase = (const char*)g_kh + lane * 8;
    const char* hnbase = (const char*)g_hnh + (h * 8 + qd * 2) * 2;

    for (;;) {
        int n = 0;
        if (lane == 0) n = atomicAdd(G_TICKET, 1);
        n = __shfl_sync(0xffffffffu, n, 0);
        if (n >= NN) return;

        const int st = ntype[n];
        const float4 qv = *(const float4*)(g_q + n * DDIM + lane * 4);
        const float2 hs = *(const float2*)(g_hsub + n * 64 + h * 8 + qd * 2);
        const float4 rv = *(const float4*)(ratt + (st * HH + h) * DKV + qd * 4);
        const float2 rh = *(const float2*)(rhatt + (st * HH + h) * HDV + qd * 2);

        const __half2 qh0 = __floats2half2_rn(qv.x, qv.y);
        const __half2 qh1 = __floats2half2_rn(qv.z, qv.w);
        const __half2 rv0h = __floats2half2_rn(rv.x, rv.y);
        const __half2 rv1h = __floats2half2_rn(rv.z, rv.w);
        const __half2 hsh = __floats2half2_rn(hs.x, hs.y);
        const __half2 rhh = __floats2half2_rn(rh.x, rh.y);

        const int b = g_off[n], e_end = g_off[n + 1];
        u64 a01 = 0ULL, a23 = 0ULL;
        float den = 0.f;

        int p = b;
        if ((p & 1) && p < e_end) {          // align for int2 pair loads
            hgx_edge(g_csr[p], khbase, hnbase,
                     qh0, qh1, rv0h, rv1h, hsh, rhh, a01, a23, den);
            p++;
        }
        for (; p + 2 <= e_end; p += 2) {
            int2 oo = *(const int2*)&g_csr[p];
            hgx_edge(oo.x, khbase, hnbase,
                     qh0, qh1, rv0h, rv1h, hsh, rhh, a01, a23, den);
            hgx_edge(oo.y, khbase, hnbase,
                     qh0, qh1, rv0h, rv1h, hsh, rhh, a01, a23, den);
        }
        if (p < e_end)
            hgx_edge(g_csr[p], khbase, hnbase,
                     qh0, qh1, rv0h, rv1h, hsh, rhh, a01, a23, den);

        float a0, a1, a2, a3;
        hgx_unpack2(a01, a0, a1);
        hgx_unpack2(a23, a2, a3);

        float inv = __fdividef(1.f, den + 1e-16f);
        float g0 = hgx_gelu(a0 * inv), g1 = hgx_gelu(a1 * inv);
        float g2 = hgx_gelu(a2 * inv), g3 = hgx_gelu(a3 * inv);

        float s = g0 + g1 + g2 + g3;
#pragma unroll
        for (int o = 16; o; o >>= 1) s += __shfl_xor_sync(0xffffffffu, s, o);
        float mean = s * (1.0f / 128.0f);

        float d0 = g0 - mean, d1 = g1 - mean, d2 = g2 - mean, d3 = g3 - mean;
        float v = d0 * d0 + d1 * d1 + d2 * d2 + d3 * d3;
#pragma unroll
        for (int o = 16; o; o >>= 1) v += __shfl_xor_sync(0xffffffffu, v, o);
        float rs = rsqrtf(v * (1.0f / 128.0f) + 1e-5f);

        int d = lane * 4;
        float4 gm = *(const float4*)(gamma + d);
        float4 bt = *(const float4*)(beta + d);
        float4 ov;
        ov.x = d0 * rs * gm.x + bt.x;
        ov.y = d1 * rs * gm.y + bt.y;
        ov.z = d2 * rs * gm.z + bt.z;
        ov.w = d3 * rs * gm.w + bt.w;
        *(float4*)(out + n * DDIM + d) = ov;
    }
}

// ---------------- launch ----------------
extern "C" void kernel_launch(void* const* d_in, const int* in_sizes, int n_in,
                              void* d_out, int out_size) {
    const float* meta_xs   = (const float*)d_in[0];
    const int*   node_type = (const int*)d_in[1];
    const int*   edge_idx  = (const int*)d_in[2];
    const float* h_mat     = (const float*)d_in[3];
    const float* sub_W     = (const float*)d_in[4];
    const float* sub_b     = (const float*)d_in[5];
    const float* neigh_W   = (const float*)d_in[6];
    const float* neigh_b   = (const float*)d_in[7];
    const float* hsub_W    = (const float*)d_in[8];
    const float* hsub_b    = (const float*)d_in[9];
    const float* hneigh_W  = (const float*)d_in[10];
    const float* hneigh_b  = (const float*)d_in[11];
    const float* rel_att   = (const float*)d_in[12];
    const float* rel_h_att = (const float*)d_in[13];
    const float* ln_gamma  = (const float*)d_in[14];
    const float* ln_beta   = (const float*)d_in[15];
    float* out = (float*)d_out;

    void* p_z;
    cudaGetSymbolAddress(&p_z, g_zeroed);
    cudaMemsetAsync(p_z, 0, (2 * NN + TT + 2) * sizeof(int));

    k_pre<<<(NN * 64 + 255) / 256, 256>>>(edge_idx, node_type, h_mat,
                                          hsub_W, hsub_b, hneigh_W, hneigh_b,
                                          sub_W, neigh_W);
    k_mid<<<K2_BLOCKS, 128>>>(meta_xs, sub_b, neigh_b, edge_idx);
    k_edge<<<EDGE_BLOCKS, 256>>>(node_type, rel_att, rel_h_att,
                                 ln_gamma, ln_beta, out);
}

// round 15
// speedup vs baseline: 1.0538x; 1.0538x over previous
#include <cuda_runtime.h>
#include <cuda_fp16.h>
#include <math.h>

#define NN 50000
#define EE 800000
#define DDIM 128
#define TT 4
#define HH 8
#define DKV 16
#define HDV 8

#define CSR_BLOCKS ((EE + 127) / 128)        // 6250
#define PROJ_BX ((NN + 127) / 128)           // 391 (128 nodes per block)
#define PROJ_BLOCKS (PROJ_BX * TT)           // 1564
#define K2_BLOCKS (1 + PROJ_BLOCKS + CSR_BLOCKS)
#define EDGE_BLOCKS (148 * 6)                // persistent grid

typedef unsigned long long u64;

// ---------------- scratch (static device memory; no allocation) ----------------
__device__ float  g_q[NN * DDIM];
__device__ __half g_kh[NN * DDIM];           // half k: tanh args AND message source
__device__ __half g_xh[NN * DDIM];           // half x (mma A operand)
__device__ float  g_hsub[NN * HH * HDV];
__device__ __half g_hnh[NN * HH * HDV];      // half h_neigh (tanh args)
__device__ __half g_Wh[2 * TT * DDIM * DDIM]; // fp16 W, [mat][t][o][k] (transposed)
__device__ int    g_zeroed[2 * NN + TT + 2]; // [deg | cnt | tcount | ticket | scandone]
#define G_DEG(i)   g_zeroed[i]
#define G_CNT(i)   g_zeroed[NN + (i)]
#define G_TC(i)    g_zeroed[2 * NN + (i)]
#define G_TICKET   (&g_zeroed[2 * NN + TT])
#define G_SCANDONE (&g_zeroed[2 * NN + TT + 1])
__device__ int    g_off[NN + 1];
__device__ int    g_csr[EE];                 // BYTE offset src*512 per CSR slot
__device__ int    g_bucket[TT * NN];

// ---------------- helpers (unique prefix, anon namespace) ----------------
namespace {
__device__ __forceinline__ float hgx_gelu(float x) {
    return 0.5f * x * (1.f + erff(x * 0.7071067811865475f));
}
__device__ __forceinline__ u64 hgx_pack2(float lo, float hi) {
    u64 r; asm("mov.b64 %0, {%1, %2};" : "=l"(r) : "f"(lo), "f"(hi)); return r;
}
__device__ __forceinline__ void hgx_unpack2(u64 v, float& lo, float& hi) {
    asm("mov.b64 {%0, %1}, %2;" : "=f"(lo), "=f"(hi) : "l"(v));
}
__device__ __forceinline__ u64 hgx_ffma2(u64 a, u64 b, u64 c) {
    u64 d; asm("fma.rn.f32x2 %0, %1, %2, %3;" : "=l"(d) : "l"(a), "l"(b), "l"(c)); return d;
}
__device__ __forceinline__ __half2 hgx_tanh2(__half2 x) {
    unsigned xi = *reinterpret_cast<unsigned*>(&x);
    unsigned yi;
    asm("tanh.approx.f16x2 %0, %1;" : "=r"(yi) : "r"(xi));
    return *reinterpret_cast<__half2*>(&yi);
}
__device__ __forceinline__ __half2 hgx_shfl_xor_h2(__half2 v, int m) {
    unsigned u = *reinterpret_cast<unsigned*>(&v);
    u = __shfl_xor_sync(0xffffffffu, u, m);
    return *reinterpret_cast<__half2*>(&u);
}

// per-edge core: one half k stream feeds tanh args AND (reconverted) message
__device__ __forceinline__ void hgx_edge(
        int o, const char* khbase, const char* hnbase,
        __half2 qh0, __half2 qh1, __half2 rv0h, __half2 rv1h,
        __half2 hsh, __half2 rhh,
        u64& a01, u64& a23, float& den) {
    const float C = 0.08838834764831845f;    // 1/(4*sqrt(8))
    uint2 khp = *(const uint2*)(khbase + (o >> 1));         // 4 half k (8B)
    unsigned hnu = *(const unsigned*)(hnbase + (o >> 2));   // 2 half hneigh (4B)
    __half2 kh0 = *reinterpret_cast<__half2*>(&khp.x);
    __half2 kh1 = *reinterpret_cast<__half2*>(&khp.y);
    __half2 hnh = *reinterpret_cast<__half2*>(&hnu);

    __half2 ta = __hmul2(hgx_tanh2(__hmul2(qh0, kh0)), rv0h);
    ta = __hfma2(hgx_tanh2(__hmul2(qh1, kh1)), rv1h, ta);
    __half2 tb = __hmul2(hgx_tanh2(__hmul2(hsh, hnh)), rhh);

    __half2 sab = __hadd2(__lows2half2(ta, tb), __highs2half2(ta, tb));
    sab = __hadd2(sab, hgx_shfl_xor_h2(sab, 1));
    sab = __hadd2(sab, hgx_shfl_xor_h2(sab, 2));

    float2 f = __half22float2(sab);
    float w = __expf(f.x * f.y * C);
    den += w;
    float2 f0 = __half22float2(kh0);
    float2 f1 = __half22float2(kh1);
    u64 w2 = hgx_pack2(w, w);
    a01 = hgx_ffma2(hgx_pack2(f0.x, f0.y), w2, a01);
    a23 = hgx_ffma2(hgx_pack2(f1.x, f1.y), w2, a23);
}
} // anonymous namespace

// ---------------- k1: h proj + x fp16 + W fp16 transpose + degree + bucketing ----------------
__global__ void k_pre(const int* __restrict__ ei, const int* __restrict__ ntype,
                      const float* __restrict__ h_mat, const float* __restrict__ xs,
                      const float* __restrict__ hsW, const float* __restrict__ hsb,
                      const float* __restrict__ hnW, const float* __restrict__ hnb,
                      const float* __restrict__ subW, const float* __restrict__ neighW) {
    __shared__ int s_cnt[TT], s_base[TT];
    int idx = blockIdx.x * blockDim.x + threadIdx.x;
    int tid = threadIdx.x;

    if (idx < NN * 64) {
        // h projections
        int n = idx >> 6, j = idx & 63;
        float s1 = hsb[j], s2 = hnb[j];
        const float* hm = h_mat + n * 8;
#pragma unroll
        for (int d = 0; d < 8; d++) {
            float v = hm[d];
            s1 += v * hsW[d * 64 + j];
            s2 += v * hnW[d * 64 + j];
        }
        g_hsub[idx] = s1;
        g_hnh[idx] = __float2half_rn(s2);

        // x -> fp16 (NN*64 float2 pairs == NN*128 floats)
        float2 xv = ((const float2*)xs)[idx];
        ((__half2*)g_xh)[idx] = __floats2half2_rn(xv.x, xv.y);
    }

    // fp16 weight transpose: g_Wh[mat][t][o][k] = W[t][k][o]
    if (idx < 2 * TT * DDIM * DDIM) {
        int mat = idx >> 16;
        int r = idx & 65535;
        int t = r >> 14;
        int rem = r & 16383;
        int o = rem >> 7;
        int k = rem & 127;
        const float* W = mat ? neighW : subW;
        g_Wh[idx] = __float2half_rn(W[t * 16384 + k * 128 + o]);
    }

    if (tid < TT) s_cnt[tid] = 0;
    __syncthreads();

    if (idx < EE) atomicAdd(&G_DEG(ei[EE + idx]), 1);

    int t = -1, pos = 0;
    if (idx < NN) {
        t = ntype[idx];
        pos = atomicAdd(&s_cnt[t], 1);
    }
    __syncthreads();
    if (tid < TT && s_cnt[tid] > 0)
        s_base[tid] = atomicAdd(&G_TC(tid), s_cnt[tid]);
    __syncthreads();
    if (idx < NN) g_bucket[t * NN + s_base[t] + pos] = idx;
}

// ---------------- k2: scan (block 0) | mma projection (128 nodes/blk) | CSR fill ----------------
__global__ __launch_bounds__(128) void k_mid(
        const float* __restrict__ subb, const float* __restrict__ neighb,
        const int* __restrict__ ei) {
    const int blk = blockIdx.x;
    const int tid = threadIdx.x;

    // ---- role 0: single-block degree prefix scan (hidden under proj blocks)
    if (blk == 0) {
        __shared__ int sums[128];
        const int CH = (NN + 127) / 128;     // 391
        int b = tid * CH;
        int e = min(b + CH, NN);
        int s = 0;
        for (int i = b; i < e; i++) s += G_DEG(i);
        sums[tid] = s;
        __syncthreads();
        for (int off = 1; off < 128; off <<= 1) {
            int v = (tid >= off) ? sums[tid - off] : 0;
            __syncthreads();
            sums[tid] += v;
            __syncthreads();
        }
        int run = sums[tid] - s;
        for (int i = b; i < e; i++) { g_off[i] = run; run += G_DEG(i); }
        if (tid == 127) g_off[NN] = sums[127];
        __syncthreads();
        if (tid == 0) {
            __threadfence();
            atomicExch(G_SCANDONE, 1);
        }
        return;
    }

    // ---- role 2 (trailing blocks): CSR fill; spin until scan published g_off
    if (blk > PROJ_BLOCKS) {
        if (tid == 0) {
            while (atomicAdd(G_SCANDONE, 0) == 0) __nanosleep(200);
        }
        __syncthreads();
        int i = (blk - 1 - PROJ_BLOCKS) * 128 + tid;
        if (i < EE) {
            int src = ei[i];
            int dst = ei[EE + i];
            int pos = g_off[dst] + atomicAdd(&G_CNT(dst), 1);
            g_csr[pos] = src * 512;          // byte offset (fp32 row scale; >>1 for kh)
        }
        return;
    }

    // ---- role 1: fp16 mma projection; block = 128 nodes of ONE type, 4 warps
    const int pb = blk - 1;
    const int t = pb / PROJ_BX;
    const int base = (pb % PROJ_BX) * 128;
    const int cnt = G_TC(t);
    if (base >= cnt) return;
    const int m = min(128, cnt - base);

    __shared__ __half sA[32 * 136];          // x subtile [node][k], stride 136
    __shared__ __half sB[4][32 * 136];       // per-warp W tile [o][k]
    __shared__ int nd[128];

    const int lane = tid & 31;
    const int warp = tid >> 5;

    nd[tid] = (tid < m) ? g_bucket[t * NN + base + tid] : 0;
    __syncthreads();

    const int g = lane >> 2;                 // 0..7
    const int c0 = (lane & 3) * 2;           // 0,2,4,6
    const int wbase = warp * 32;
    __half* sBw = sB[warp];

    for (int mat = 0; mat < 2; mat++) {
        const __half* Wh = g_Wh + ((size_t)mat * TT + t) * (DDIM * DDIM) + (size_t)wbase * DDIM;

        // stage this warp's W tile ONCE per mat: 32 o-rows x 128 k halfs
#pragma unroll
        for (int it = 0; it < 16; it++) {
            int idx = it * 32 + lane;        // 0..511 chunks of 8 halfs
            int o = idx >> 4;
            int ch = idx & 15;
            *(uint4*)&sBw[o * 136 + ch * 8] = *(const uint4*)(Wh + o * DDIM + ch * 8);
        }
        __syncwarp();

        const float* bias = (mat == 0 ? subb : neighb) + t * DDIM;

        for (int sub = 0; sub < 4; sub++) {
            int nb = sub * 32;
            if (nb >= m) break;              // m is block-uniform
            __syncthreads();                 // all warps done with previous sA
            // fill sA with nodes [nb, nb+32): 128 threads x 16 half2 each
#pragma unroll
            for (int i = 0; i < 16; i++) {
                int idx2 = i * 128 + tid;    // 0..2047
                int node = idx2 >> 6;        // 0..31
                int dp = idx2 & 63;          // half2 index in row
                int gn = nb + node;
                __half2 v = (gn < m) ? *(const __half2*)(g_xh + (size_t)nd[gn] * DDIM + dp * 2)
                                     : __floats2half2_rn(0.f, 0.f);
                *(__half2*)&sA[node * 136 + dp * 2] = v;
            }
            __syncthreads();

            float acc[8][4];                 // [nt*2+mt][4]
#pragma unroll
            for (int i = 0; i < 8; i++)
#pragma unroll
                for (int j = 0; j < 4; j++) acc[i][j] = 0.f;

#pragma unroll
            for (int ks = 0; ks < 8; ks++) {
                int kb = ks * 16;
                unsigned a[2][4], bf[4][2];
#pragma unroll
                for (int mt = 0; mt < 2; mt++) {
                    int r0 = mt * 16 + g;
                    a[mt][0] = *(const unsigned*)&sA[r0 * 136 + kb + c0];
                    a[mt][1] = *(const unsigned*)&sA[(r0 + 8) * 136 + kb + c0];
                    a[mt][2] = *(const unsigned*)&sA[r0 * 136 + kb + c0 + 8];
                    a[mt][3] = *(const unsigned*)&sA[(r0 + 8) * 136 + kb + c0 + 8];
                }
#pragma unroll
                for (int nt = 0; nt < 4; nt++) {
                    int n = nt * 8 + g;
                    bf[nt][0] = *(const unsigned*)&sBw[n * 136 + kb + c0];
                    bf[nt][1] = *(const unsigned*)&sBw[n * 136 + kb + c0 + 8];
                }
#pragma unroll
                for (int nt = 0; nt < 4; nt++)
#pragma unroll
                    for (int mt = 0; mt < 2; mt++) {
                        float* c = acc[nt * 2 + mt];
                        asm volatile(
                            "mma.sync.aligned.m16n8k16.row.col.f32.f16.f16.f32 "
                            "{%0,%1,%2,%3}, {%4,%5,%6,%7}, {%8,%9}, {%0,%1,%2,%3};\n"
                            : "+f"(c[0]), "+f"(c[1]), "+f"(c[2]), "+f"(c[3])
                            : "r"(a[mt][0]), "r"(a[mt][1]), "r"(a[mt][2]), "r"(a[mt][3]),
                              "r"(bf[nt][0]), "r"(bf[nt][1]));
                    }
            }

            // epilogue: bias + store (q fp32, k half)
#pragma unroll
            for (int nt = 0; nt < 4; nt++) {
                int col = wbase + nt * 8 + c0;
                float2 bb = *(const float2*)(bias + col);
#pragma unroll
                for (int mt = 0; mt < 2; mt++) {
                    float* c = acc[nt * 2 + mt];
                    int r0 = nb + mt * 16 + g, r1 = r0 + 8;
                    if (mat == 0) {
                        if (r0 < m) *(float2*)(g_q + (size_t)nd[r0] * DDIM + col) =
                            make_float2(c[0] + bb.x, c[1] + bb.y);
                        if (r1 < m) *(float2*)(g_q + (size_t)nd[r1] * DDIM + col) =
                            make_float2(c[2] + bb.x, c[3] + bb.y);
                    } else {
                        if (r0 < m) *(__half2*)(g_kh + (size_t)nd[r0] * DDIM + col) =
                            __floats2half2_rn(c[0] + bb.x, c[1] + bb.y);
                        if (r1 < m) *(__half2*)(g_kh + (size_t)nd[r1] * DDIM + col) =
                            __floats2half2_rn(c[2] + bb.x, c[3] + bb.y);
                    }
                }
            }
        }
    }
}

// ---------------- fused attention + softmax + aggregate + gelu + LN ----------------
// PERSISTENT: warps pull dst nodes via global ticket; lane owns 4 dims (head = lane>>2)
__global__ __launch_bounds__(256, 6) void k_edge(
        const int* __restrict__ ntype,
        const float* __restrict__ ratt, const float* __restrict__ rhatt,
        const float* __restrict__ gamma, const float* __restrict__ beta,
        float* __restrict__ out) {
    const int lane = threadIdx.x & 31;
    const int h = lane >> 2;
    const int qd = lane & 3;

    const char* khbase = (const char*)g_kh + lane * 8;
    const char* hnbase = (const char*)g_hnh + (h * 8 + qd * 2) * 2;

    for (;;) {
        int n = 0;
        if (lane == 0) n = atomicAdd(G_TICKET, 1);
        n = __shfl_sync(0xffffffffu, n, 0);
        if (n >= NN) return;

        const int st = ntype[n];
        const float4 qv = *(const float4*)(g_q + n * DDIM + lane * 4);
        const float2 hs = *(const float2*)(g_hsub + n * 64 + h * 8 + qd * 2);
        const float4 rv = *(const float4*)(ratt + (st * HH + h) * DKV + qd * 4);
        const float2 rh = *(const float2*)(rhatt + (st * HH + h) * HDV + qd * 2);

        const __half2 qh0 = __floats2half2_rn(qv.x, qv.y);
        const __half2 qh1 = __floats2half2_rn(qv.z, qv.w);
        const __half2 rv0h = __floats2half2_rn(rv.x, rv.y);
        const __half2 rv1h = __floats2half2_rn(rv.z, rv.w);
        const __half2 hsh = __floats2half2_rn(hs.x, hs.y);
        const __half2 rhh = __floats2half2_rn(rh.x, rh.y);

        const int b = g_off[n], e_end = g_off[n + 1];
        u64 a01 = 0ULL, a23 = 0ULL;
        float den = 0.f;

        int p = b;
        if ((p & 1) && p < e_end) {          // align for int2 pair loads
            hgx_edge(g_csr[p], khbase, hnbase,
                     qh0, qh1, rv0h, rv1h, hsh, rhh, a01, a23, den);
            p++;
        }
        for (; p + 2 <= e_end; p += 2) {
            int2 oo = *(const int2*)&g_csr[p];
            hgx_edge(oo.x, khbase, hnbase,
                     qh0, qh1, rv0h, rv1h, hsh, rhh, a01, a23, den);
            hgx_edge(oo.y, khbase, hnbase,
                     qh0, qh1, rv0h, rv1h, hsh, rhh, a01, a23, den);
        }
        if (p < e_end)
            hgx_edge(g_csr[p], khbase, hnbase,
                     qh0, qh1, rv0h, rv1h, hsh, rhh, a01, a23, den);

        float a0, a1, a2, a3;
        hgx_unpack2(a01, a0, a1);
        hgx_unpack2(a23, a2, a3);

        float inv = __fdividef(1.f, den + 1e-16f);
        float g0 = hgx_gelu(a0 * inv), g1 = hgx_gelu(a1 * inv);
        float g2 = hgx_gelu(a2 * inv), g3 = hgx_gelu(a3 * inv);

        float s = g0 + g1 + g2 + g3;
#pragma unroll
        for (int o = 16; o; o >>= 1) s += __shfl_xor_sync(0xffffffffu, s, o);
        float mean = s * (1.0f / 128.0f);

        float d0 = g0 - mean, d1 = g1 - mean, d2 = g2 - mean, d3 = g3 - mean;
        float v = d0 * d0 + d1 * d1 + d2 * d2 + d3 * d3;
#pragma unroll
        for (int o = 16; o; o >>= 1) v += __shfl_xor_sync(0xffffffffu, v, o);
        float rs = rsqrtf(v * (1.0f / 128.0f) + 1e-5f);

        int d = lane * 4;
        float4 gm = *(const float4*)(gamma + d);
        float4 bt = *(const float4*)(beta + d);
        float4 ov;
        ov.x = d0 * rs * gm.x + bt.x;
        ov.y = d1 * rs * gm.y + bt.y;
        ov.z = d2 * rs * gm.z + bt.z;
        ov.w = d3 * rs * gm.w + bt.w;
        *(float4*)(out + n * DDIM + d) = ov;
    }
}

// ---------------- launch ----------------
extern "C" void kernel_launch(void* const* d_in, const int* in_sizes, int n_in,
                              void* d_out, int out_size) {
    const float* meta_xs   = (const float*)d_in[0];
    const int*   node_type = (const int*)d_in[1];
    const int*   edge_idx  = (const int*)d_in[2];
    const float* h_mat     = (const float*)d_in[3];
    const float* sub_W     = (const float*)d_in[4];
    const float* sub_b     = (const float*)d_in[5];
    const float* neigh_W   = (const float*)d_in[6];
    const float* neigh_b   = (const float*)d_in[7];
    const float* hsub_W    = (const float*)d_in[8];
    const float* hsub_b    = (const float*)d_in[9];
    const float* hneigh_W  = (const float*)d_in[10];
    const float* hneigh_b  = (const float*)d_in[11];
    const float* rel_att   = (const float*)d_in[12];
    const float* rel_h_att = (const float*)d_in[13];
    const float* ln_gamma  = (const float*)d_in[14];
    const float* ln_beta   = (const float*)d_in[15];
    float* out = (float*)d_out;

    void* p_z;
    cudaGetSymbolAddress(&p_z, g_zeroed);
    cudaMemsetAsync(p_z, 0, (2 * NN + TT + 2) * sizeof(int));

    k_pre<<<(NN * 64 + 255) / 256, 256>>>(edge_idx, node_type, h_mat, meta_xs,
                                          hsub_W, hsub_b, hneigh_W, hneigh_b,
                                          sub_W, neigh_W);
    k_mid<<<K2_BLOCKS, 128>>>(sub_b, neigh_b, edge_idx);
    k_edge<<<EDGE_BLOCKS, 256>>>(node_type, rel_att, rel_h_att,
                                 ln_gamma, ln_beta, out);
}

// round 16
// speedup vs baseline: 1.4276x; 1.3547x over previous
#include <cuda_runtime.h>
#include <cuda_fp16.h>
#include <math.h>

#define NN 50000
#define EE 800000
#define DDIM 128
#define TT 4
#define HH 8
#define DKV 16
#define HDV 8

#define CSR_BLOCKS ((EE + 127) / 128)        // 6250
#define PROJ_BX ((NN + 127) / 128)           // 391 (128 nodes per block)
#define PROJ_BLOCKS (PROJ_BX * TT)           // 1564
#define K2_BLOCKS (1 + PROJ_BLOCKS + CSR_BLOCKS)
#define EDGE_BLOCKS (148 * 6)                // persistent grid

typedef unsigned long long u64;

// ---------------- scratch (static device memory; no allocation) ----------------
__device__ float  g_q[NN * DDIM];
__device__ __half g_kh[NN * DDIM];           // half k: tanh args AND message source
__device__ __half g_xh[NN * DDIM];           // half x (mma A operand)
__device__ float  g_hsub[NN * HH * HDV];
__device__ __half g_hnh[NN * HH * HDV];      // half h_neigh (tanh args)
__device__ __half g_Wh[2 * TT * DDIM * DDIM]; // fp16 W, [mat][t][o][k] (transposed)
__device__ int    g_zeroed[2 * NN + TT + 2]; // [deg | cnt | tcount | ticket | scandone]
#define G_DEG(i)   g_zeroed[i]
#define G_CNT(i)   g_zeroed[NN + (i)]
#define G_TC(i)    g_zeroed[2 * NN + (i)]
#define G_TICKET   (&g_zeroed[2 * NN + TT])
#define G_SCANDONE (&g_zeroed[2 * NN + TT + 1])
__device__ int    g_off[NN + 1];
__device__ int    g_csr[EE];                 // BYTE offset src*512 per CSR slot
__device__ int    g_bucket[TT * NN];

// ---------------- helpers (unique prefix, anon namespace) ----------------
namespace {
__device__ __forceinline__ float hgx_gelu(float x) {
    return 0.5f * x * (1.f + erff(x * 0.7071067811865475f));
}
__device__ __forceinline__ u64 hgx_pack2(float lo, float hi) {
    u64 r; asm("mov.b64 %0, {%1, %2};" : "=l"(r) : "f"(lo), "f"(hi)); return r;
}
__device__ __forceinline__ void hgx_unpack2(u64 v, float& lo, float& hi) {
    asm("mov.b64 {%0, %1}, %2;" : "=f"(lo), "=f"(hi) : "l"(v));
}
__device__ __forceinline__ u64 hgx_ffma2(u64 a, u64 b, u64 c) {
    u64 d; asm("fma.rn.f32x2 %0, %1, %2, %3;" : "=l"(d) : "l"(a), "l"(b), "l"(c)); return d;
}
__device__ __forceinline__ __half2 hgx_tanh2(__half2 x) {
    unsigned xi = *reinterpret_cast<unsigned*>(&x);
    unsigned yi;
    asm("tanh.approx.f16x2 %0, %1;" : "=r"(yi) : "r"(xi));
    return *reinterpret_cast<__half2*>(&yi);
}
__device__ __forceinline__ __half2 hgx_shfl_xor_h2(__half2 v, int m) {
    unsigned u = *reinterpret_cast<unsigned*>(&v);
    u = __shfl_xor_sync(0xffffffffu, u, m);
    return *reinterpret_cast<__half2*>(&u);
}

// math-only per-edge core (operands preloaded by caller for explicit MLP)
__device__ __forceinline__ void hgx_edge_math(
        uint2 khp, unsigned hnu,
        __half2 qh0, __half2 qh1, __half2 rv0h, __half2 rv1h,
        __half2 hsh, __half2 rhh,
        u64& a01, u64& a23, float& den) {
    const float C = 0.08838834764831845f;    // 1/(4*sqrt(8))
    __half2 kh0 = *reinterpret_cast<__half2*>(&khp.x);
    __half2 kh1 = *reinterpret_cast<__half2*>(&khp.y);
    __half2 hnh = *reinterpret_cast<__half2*>(&hnu);

    __half2 ta = __hmul2(hgx_tanh2(__hmul2(qh0, kh0)), rv0h);
    ta = __hfma2(hgx_tanh2(__hmul2(qh1, kh1)), rv1h, ta);
    __half2 tb = __hmul2(hgx_tanh2(__hmul2(hsh, hnh)), rhh);

    __half2 sab = __hadd2(__lows2half2(ta, tb), __highs2half2(ta, tb));
    sab = __hadd2(sab, hgx_shfl_xor_h2(sab, 1));
    sab = __hadd2(sab, hgx_shfl_xor_h2(sab, 2));

    float2 f = __half22float2(sab);
    float w = __expf(f.x * f.y * C);
    den += w;
    float2 f0 = __half22float2(kh0);
    float2 f1 = __half22float2(kh1);
    u64 w2 = hgx_pack2(w, w);
    a01 = hgx_ffma2(hgx_pack2(f0.x, f0.y), w2, a01);
    a23 = hgx_ffma2(hgx_pack2(f1.x, f1.y), w2, a23);
}
} // anonymous namespace

// ---------------- k1: h proj + x fp16 + W fp16 transpose + degree + bucketing ----------------
__global__ void k_pre(const int* __restrict__ ei, const int* __restrict__ ntype,
                      const float* __restrict__ h_mat, const float* __restrict__ xs,
                      const float* __restrict__ hsW, const float* __restrict__ hsb,
                      const float* __restrict__ hnW, const float* __restrict__ hnb,
                      const float* __restrict__ subW, const float* __restrict__ neighW) {
    __shared__ int s_cnt[TT], s_base[TT];
    int idx = blockIdx.x * blockDim.x + threadIdx.x;
    int tid = threadIdx.x;

    if (idx < NN * 64) {
        // h projections (vectorized h_mat row load)
        int n = idx >> 6, j = idx & 63;
        const float4 hm0 = *(const float4*)(h_mat + n * 8);
        const float4 hm1 = *(const float4*)(h_mat + n * 8 + 4);
        float s1 = hsb[j], s2 = hnb[j];
        s1 += hm0.x * hsW[0 * 64 + j] + hm0.y * hsW[1 * 64 + j]
            + hm0.z * hsW[2 * 64 + j] + hm0.w * hsW[3 * 64 + j]
            + hm1.x * hsW[4 * 64 + j] + hm1.y * hsW[5 * 64 + j]
            + hm1.z * hsW[6 * 64 + j] + hm1.w * hsW[7 * 64 + j];
        s2 += hm0.x * hnW[0 * 64 + j] + hm0.y * hnW[1 * 64 + j]
            + hm0.z * hnW[2 * 64 + j] + hm0.w * hnW[3 * 64 + j]
            + hm1.x * hnW[4 * 64 + j] + hm1.y * hnW[5 * 64 + j]
            + hm1.z * hnW[6 * 64 + j] + hm1.w * hnW[7 * 64 + j];
        g_hsub[idx] = s1;
        g_hnh[idx] = __float2half_rn(s2);

        // x -> fp16 (NN*64 float2 pairs == NN*128 floats)
        float2 xv = ((const float2*)xs)[idx];
        ((__half2*)g_xh)[idx] = __floats2half2_rn(xv.x, xv.y);
    }

    // fp16 weight transpose: g_Wh[mat][t][o][k] = W[t][k][o]
    if (idx < 2 * TT * DDIM * DDIM) {
        int mat = idx >> 16;
        int r = idx & 65535;
        int t = r >> 14;
        int rem = r & 16383;
        int o = rem >> 7;
        int k = rem & 127;
        const float* W = mat ? neighW : subW;
        g_Wh[idx] = __float2half_rn(W[t * 16384 + k * 128 + o]);
    }

    if (tid < TT) s_cnt[tid] = 0;
    __syncthreads();

    if (idx < EE) atomicAdd(&G_DEG(ei[EE + idx]), 1);

    int t = -1, pos = 0;
    if (idx < NN) {
        t = ntype[idx];
        pos = atomicAdd(&s_cnt[t], 1);
    }
    __syncthreads();
    if (tid < TT && s_cnt[tid] > 0)
        s_base[tid] = atomicAdd(&G_TC(tid), s_cnt[tid]);
    __syncthreads();
    if (idx < NN) g_bucket[t * NN + s_base[t] + pos] = idx;
}

// ---------------- k2: scan (block 0) | mma projection (128 nodes/blk) | CSR fill ----------------
__global__ __launch_bounds__(128) void k_mid(
        const float* __restrict__ subb, const float* __restrict__ neighb,
        const int* __restrict__ ei) {
    const int blk = blockIdx.x;
    const int tid = threadIdx.x;

    // ---- role 0: single-block degree prefix scan (int4-vectorized)
    if (blk == 0) {
        __shared__ int sums[128];
        const int CH = 392;                  // 128*392 >= NN, 16B-aligned chunks
        int b = tid * CH;
        int e = min(b + CH, NN);
        int s = 0;
        int i = b;
        for (; i + 4 <= e; i += 4) {
            int4 v = *(const int4*)&G_DEG(i);
            s += v.x + v.y + v.z + v.w;
        }
        for (; i < e; i++) s += G_DEG(i);
        sums[tid] = s;
        __syncthreads();
        for (int off = 1; off < 128; off <<= 1) {
            int v = (tid >= off) ? sums[tid - off] : 0;
            __syncthreads();
            sums[tid] += v;
            __syncthreads();
        }
        int run = sums[tid] - s;
        i = b;
        for (; i + 4 <= e; i += 4) {
            int4 v = *(const int4*)&G_DEG(i);
            int4 o;
            o.x = run;          run += v.x;
            o.y = run;          run += v.y;
            o.z = run;          run += v.z;
            o.w = run;          run += v.w;
            *(int4*)&g_off[i] = o;
        }
        for (; i < e; i++) { g_off[i] = run; run += G_DEG(i); }
        if (tid == 127) g_off[NN] = sums[127];
        __syncthreads();
        if (tid == 0) {
            __threadfence();
            atomicExch(G_SCANDONE, 1);
        }
        return;
    }

    // ---- role 2 (trailing blocks): CSR fill; spin until scan published g_off
    if (blk > PROJ_BLOCKS) {
        if (tid == 0) {
            while (atomicAdd(G_SCANDONE, 0) == 0) __nanosleep(200);
        }
        __syncthreads();
        int i = (blk - 1 - PROJ_BLOCKS) * 128 + tid;
        if (i < EE) {
            int src = ei[i];
            int dst = ei[EE + i];
            int pos = g_off[dst] + atomicAdd(&G_CNT(dst), 1);
            g_csr[pos] = src * 512;          // byte offset (fp32 row scale; >>1 for kh)
        }
        return;
    }

    // ---- role 1: fp16 mma projection; block = 128 nodes of ONE type, 4 warps
    const int pb = blk - 1;
    const int t = pb / PROJ_BX;
    const int base = (pb % PROJ_BX) * 128;
    const int cnt = G_TC(t);
    if (base >= cnt) return;
    const int m = min(128, cnt - base);

    __shared__ __half sA[32 * 136];          // x subtile [node][k], stride 136
    __shared__ __half sB[4][32 * 136];       // per-warp W tile [o][k]
    __shared__ int nd[128];

    const int lane = tid & 31;
    const int warp = tid >> 5;

    nd[tid] = (tid < m) ? g_bucket[t * NN + base + tid] : 0;
    __syncthreads();

    const int g = lane >> 2;                 // 0..7
    const int c0 = (lane & 3) * 2;           // 0,2,4,6
    const int wbase = warp * 32;
    __half* sBw = sB[warp];

    for (int mat = 0; mat < 2; mat++) {
        const __half* Wh = g_Wh + ((size_t)mat * TT + t) * (DDIM * DDIM) + (size_t)wbase * DDIM;

        // stage this warp's W tile ONCE per mat: 32 o-rows x 128 k halfs
#pragma unroll
        for (int it = 0; it < 16; it++) {
            int idx = it * 32 + lane;        // 0..511 chunks of 8 halfs
            int o = idx >> 4;
            int ch = idx & 15;
            *(uint4*)&sBw[o * 136 + ch * 8] = *(const uint4*)(Wh + o * DDIM + ch * 8);
        }
        __syncwarp();

        const float* bias = (mat == 0 ? subb : neighb) + t * DDIM;

        for (int sub = 0; sub < 4; sub++) {
            int nb = sub * 32;
            if (nb >= m) break;              // m is block-uniform
            __syncthreads();                 // all warps done with previous sA
            // fill sA with nodes [nb, nb+32): 128 threads x 16 half2 each
#pragma unroll
            for (int i = 0; i < 16; i++) {
                int idx2 = i * 128 + tid;    // 0..2047
                int node = idx2 >> 6;        // 0..31
                int dp = idx2 & 63;          // half2 index in row
                int gn = nb + node;
                __half2 v = (gn < m) ? *(const __half2*)(g_xh + (size_t)nd[gn] * DDIM + dp * 2)
                                     : __floats2half2_rn(0.f, 0.f);
                *(__half2*)&sA[node * 136 + dp * 2] = v;
            }
            __syncthreads();

            float acc[8][4];                 // [nt*2+mt][4]
#pragma unroll
            for (int i = 0; i < 8; i++)
#pragma unroll
                for (int j = 0; j < 4; j++) acc[i][j] = 0.f;

#pragma unroll
            for (int ks = 0; ks < 8; ks++) {
                int kb = ks * 16;
                unsigned a[2][4], bf[4][2];
#pragma unroll
                for (int mt = 0; mt < 2; mt++) {
                    int r0 = mt * 16 + g;
                    a[mt][0] = *(const unsigned*)&sA[r0 * 136 + kb + c0];
                    a[mt][1] = *(const unsigned*)&sA[(r0 + 8) * 136 + kb + c0];
                    a[mt][2] = *(const unsigned*)&sA[r0 * 136 + kb + c0 + 8];
                    a[mt][3] = *(const unsigned*)&sA[(r0 + 8) * 136 + kb + c0 + 8];
                }
#pragma unroll
                for (int nt = 0; nt < 4; nt++) {
                    int n = nt * 8 + g;
                    bf[nt][0] = *(const unsigned*)&sBw[n * 136 + kb + c0];
                    bf[nt][1] = *(const unsigned*)&sBw[n * 136 + kb + c0 + 8];
                }
#pragma unroll
                for (int nt = 0; nt < 4; nt++)
#pragma unroll
                    for (int mt = 0; mt < 2; mt++) {
                        float* c = acc[nt * 2 + mt];
                        asm volatile(
                            "mma.sync.aligned.m16n8k16.row.col.f32.f16.f16.f32 "
                            "{%0,%1,%2,%3}, {%4,%5,%6,%7}, {%8,%9}, {%0,%1,%2,%3};\n"
                            : "+f"(c[0]), "+f"(c[1]), "+f"(c[2]), "+f"(c[3])
                            : "r"(a[mt][0]), "r"(a[mt][1]), "r"(a[mt][2]), "r"(a[mt][3]),
                              "r"(bf[nt][0]), "r"(bf[nt][1]));
                    }
            }

            // epilogue: bias + store (q fp32, k half)
#pragma unroll
            for (int nt = 0; nt < 4; nt++) {
                int col = wbase + nt * 8 + c0;
                float2 bb = *(const float2*)(bias + col);
#pragma unroll
                for (int mt = 0; mt < 2; mt++) {
                    float* c = acc[nt * 2 + mt];
                    int r0 = nb + mt * 16 + g, r1 = r0 + 8;
                    if (mat == 0) {
                        if (r0 < m) *(float2*)(g_q + (size_t)nd[r0] * DDIM + col) =
                            make_float2(c[0] + bb.x, c[1] + bb.y);
                        if (r1 < m) *(float2*)(g_q + (size_t)nd[r1] * DDIM + col) =
                            make_float2(c[2] + bb.x, c[3] + bb.y);
                    } else {
                        if (r0 < m) *(__half2*)(g_kh + (size_t)nd[r0] * DDIM + col) =
                            __floats2half2_rn(c[0] + bb.x, c[1] + bb.y);
                        if (r1 < m) *(__half2*)(g_kh + (size_t)nd[r1] * DDIM + col) =
                            __floats2half2_rn(c[2] + bb.x, c[3] + bb.y);
                    }
                }
            }
        }
    }
}

// ---------------- fused attention + softmax + aggregate + gelu + LN ----------------
// PERSISTENT: warps pull 4-node chunks via global ticket; lane owns 4 dims (head = lane>>2)
__global__ __launch_bounds__(256, 6) void k_edge(
        const int* __restrict__ ntype,
        const float* __restrict__ ratt, const float* __restrict__ rhatt,
        const float* __restrict__ gamma, const float* __restrict__ beta,
        float* __restrict__ out) {
    const int lane = threadIdx.x & 31;
    const int h = lane >> 2;
    const int qd = lane & 3;

    const char* khbase = (const char*)g_kh + lane * 8;
    const char* hnbase = (const char*)g_hnh + (h * 8 + qd * 2) * 2;

    for (;;) {
        int n0 = 0;
        if (lane == 0) n0 = atomicAdd(G_TICKET, 4);
        n0 = __shfl_sync(0xffffffffu, n0, 0);
        if (n0 >= NN) return;
        const int n_end = min(n0 + 4, NN);

        for (int n = n0; n < n_end; n++) {
            const int st = ntype[n];
            const float4 qv = *(const float4*)(g_q + n * DDIM + lane * 4);
            const float2 hs = *(const float2*)(g_hsub + n * 64 + h * 8 + qd * 2);
            const float4 rv = *(const float4*)(ratt + (st * HH + h) * DKV + qd * 4);
            const float2 rh = *(const float2*)(rhatt + (st * HH + h) * HDV + qd * 2);

            const __half2 qh0 = __floats2half2_rn(qv.x, qv.y);
            const __half2 qh1 = __floats2half2_rn(qv.z, qv.w);
            const __half2 rv0h = __floats2half2_rn(rv.x, rv.y);
            const __half2 rv1h = __floats2half2_rn(rv.z, rv.w);
            const __half2 hsh = __floats2half2_rn(hs.x, hs.y);
            const __half2 rhh = __floats2half2_rn(rh.x, rh.y);

            const int b = g_off[n], e_end = g_off[n + 1];
            u64 a01 = 0ULL, a23 = 0ULL;
            float den = 0.f;

            int p = b;
            if ((p & 1) && p < e_end) {      // align for int2 pair loads
                int o0 = g_csr[p];
                uint2 khp0 = *(const uint2*)(khbase + (o0 >> 1));
                unsigned hnu0 = *(const unsigned*)(hnbase + (o0 >> 2));
                hgx_edge_math(khp0, hnu0, qh0, qh1, rv0h, rv1h, hsh, rhh, a01, a23, den);
                p++;
            }
            for (; p + 2 <= e_end; p += 2) {
                int2 oo = *(const int2*)&g_csr[p];
                // all 4 loads issued before any math (MLP=4)
                uint2 khp0 = *(const uint2*)(khbase + (oo.x >> 1));
                uint2 khp1 = *(const uint2*)(khbase + (oo.y >> 1));
                unsigned hnu0 = *(const unsigned*)(hnbase + (oo.x >> 2));
                unsigned hnu1 = *(const unsigned*)(hnbase + (oo.y >> 2));
                hgx_edge_math(khp0, hnu0, qh0, qh1, rv0h, rv1h, hsh, rhh, a01, a23, den);
                hgx_edge_math(khp1, hnu1, qh0, qh1, rv0h, rv1h, hsh, rhh, a01, a23, den);
            }
            if (p < e_end) {
                int o0 = g_csr[p];
                uint2 khp0 = *(const uint2*)(khbase + (o0 >> 1));
                unsigned hnu0 = *(const unsigned*)(hnbase + (o0 >> 2));
                hgx_edge_math(khp0, hnu0, qh0, qh1, rv0h, rv1h, hsh, rhh, a01, a23, den);
            }

            float a0, a1, a2, a3;
            hgx_unpack2(a01, a0, a1);
            hgx_unpack2(a23, a2, a3);

            float inv = __fdividef(1.f, den + 1e-16f);
            float g0 = hgx_gelu(a0 * inv), g1 = hgx_gelu(a1 * inv);
            float g2 = hgx_gelu(a2 * inv), g3 = hgx_gelu(a3 * inv);

            float s = g0 + g1 + g2 + g3;
#pragma unroll
            for (int o = 16; o; o >>= 1) s += __shfl_xor_sync(0xffffffffu, s, o);
            float mean = s * (1.0f / 128.0f);

            float d0 = g0 - mean, d1 = g1 - mean, d2 = g2 - mean, d3 = g3 - mean;
            float v = d0 * d0 + d1 * d1 + d2 * d2 + d3 * d3;
#pragma unroll
            for (int o = 16; o; o >>= 1) v += __shfl_xor_sync(0xffffffffu, v, o);
            float rs = rsqrtf(v * (1.0f / 128.0f) + 1e-5f);

            int d = lane * 4;
            float4 gm = *(const float4*)(gamma + d);
            float4 bt = *(const float4*)(beta + d);
            float4 ov;
            ov.x = d0 * rs * gm.x + bt.x;
            ov.y = d1 * rs * gm.y + bt.y;
            ov.z = d2 * rs * gm.z + bt.z;
            ov.w = d3 * rs * gm.w + bt.w;
            *(float4*)(out + n * DDIM + d) = ov;
        }
    }
}

// ---------------- launch ----------------
extern "C" void kernel_launch(void* const* d_in, const int* in_sizes, int n_in,
                              void* d_out, int out_size) {
    const float* meta_xs   = (const float*)d_in[0];
    const int*   node_type = (const int*)d_in[1];
    const int*   edge_idx  = (const int*)d_in[2];
    const float* h_mat     = (const float*)d_in[3];
    const float* sub_W     = (const float*)d_in[4];
    const float* sub_b     = (const float*)d_in[5];
    const float* neigh_W   = (const float*)d_in[6];
    const float* neigh_b   = (const float*)d_in[7];
    const float* hsub_W    = (const float*)d_in[8];
    const float* hsub_b    = (const float*)d_in[9];
    const float* hneigh_W  = (const float*)d_in[10];
    const float* hneigh_b  = (const float*)d_in[11];
    const float* rel_att   = (const float*)d_in[12];
    const float* rel_h_att = (const float*)d_in[13];
    const float* ln_gamma  = (const float*)d_in[14];
    const float* ln_beta   = (const float*)d_in[15];
    float* out = (float*)d_out;

    void* p_z;
    cudaGetSymbolAddress(&p_z, g_zeroed);
    cudaMemsetAsync(p_z, 0, (2 * NN + TT + 2) * sizeof(int));

    k_pre<<<(NN * 64 + 255) / 256, 256>>>(edge_idx, node_type, h_mat, meta_xs,
                                          hsub_W, hsub_b, hneigh_W, hneigh_b,
                                          sub_W, neigh_W);
    k_mid<<<K2_BLOCKS, 128>>>(sub_b, neigh_b, edge_idx);
    k_edge<<<EDGE_BLOCKS, 256>>>(node_type, rel_att, rel_h_att,
                                 ln_gamma, ln_beta, out);
}